// round 15
// baseline (speedup 1.0000x reference)
#include <cuda_runtime.h>
#include <cuda_fp16.h>
#include <cstdint>

// Problem constants
#define NROWS 8192          // n = 2*B
#define BROWS 4096          // B
#define DDIM  256           // feature dim
#define BLK   128           // tile edge
#define NT    64            // NROWS/BLK
#define NTRI  (NT*(NT+1)/2) // 2080 upper-triangular tiles
#define KC    64            // k columns per chunk (128B of fp16)
#define NCH   (DDIM/KC)     // 4 chunks per tile
#define ROWB  144           // smem row stride bytes (128B data + 16B pad)
#define MATB  (BLK*ROWB)    // 18432 B per matrix buffer
#define STAGEB (2*MATB)     // 36864 B per stage (A, B)
#define NSTAGE 3
#define DYN_SMEM (NSTAGE*STAGEB) // 110592 B
#define PREPB 256           // prep blocks

// Device scratch (no allocations allowed)
__device__ float  g_sq[NROWS];
__device__ float  g_colpart[PREPB][DDIM];
__device__ double g_s1part[PREPB];
__device__ double g_result;
__device__ float  g_scale;     // 1/(16*bandwidth)
__device__ __half g_h[NROWS * DDIM];
__device__ unsigned int g_prep_count = 0;
__device__ unsigned int g_pair_count = 0;

// ---------------------------------------------------------------------------
__device__ __forceinline__ uint32_t smem_u32(const void* p) {
    uint32_t a;
    asm("{ .reg .u64 t; cvta.to.shared.u64 t, %1; cvt.u32.u64 %0, t; }"
        : "=r"(a) : "l"(p));
    return a;
}

__device__ __forceinline__ void ldsm4(uint32_t* r, uint32_t addr) {
    asm volatile("ldmatrix.sync.aligned.m8n8.x4.shared.b16 {%0,%1,%2,%3}, [%4];"
                 : "=r"(r[0]), "=r"(r[1]), "=r"(r[2]), "=r"(r[3]) : "r"(addr));
}

__device__ __forceinline__ void mma16816(float* c, const uint32_t* a,
                                         uint32_t b0, uint32_t b1) {
    asm volatile(
        "mma.sync.aligned.m16n8k16.row.col.f32.f16.f16.f32 "
        "{%0,%1,%2,%3}, {%4,%5,%6,%7}, {%8,%9}, {%0,%1,%2,%3};"
        : "+f"(c[0]), "+f"(c[1]), "+f"(c[2]), "+f"(c[3])
        : "r"(a[0]), "r"(a[1]), "r"(a[2]), "r"(a[3]), "r"(b0), "r"(b1));
}

__device__ __forceinline__ float ex2f(float x) {
    float r;
    asm("ex2.approx.ftz.f32 %0, %1;" : "=f"(r) : "f"(x));
    return r;
}

#define CP_ASYNC16(dst, src) \
    asm volatile("cp.async.cg.shared.global [%0], [%1], 16;" \
                 :: "r"(dst), "l"(src) : "memory")
#define CP_COMMIT() asm volatile("cp.async.commit_group;" ::: "memory")
#define CP_WAIT1()  asm volatile("cp.async.wait_group 1;" ::: "memory")

// ---------------------------------------------------------------------------
// Fused prep: row norms, per-block column partials + s1 partials, fp16 cast.
// LAST block reduces partials -> bandwidth -> g_scale, zeroes g_result.
__global__ void prep_kernel(const float* __restrict__ src,
                            const float* __restrict__ tgt) {
    __shared__ float  csum_s[8][DDIM];
    __shared__ double s1_s[8];
    __shared__ double red_d[256];
    __shared__ bool   is_last;

    int tid  = threadIdx.x;
    int lane = tid & 31;
    int w    = tid >> 5;
    int b    = blockIdx.x;

    float csum[8] = {0, 0, 0, 0, 0, 0, 0, 0};
    double s1 = 0.0;

    #pragma unroll
    for (int i = 0; i < 4; i++) {
        int r = b * 32 + w * 4 + i;
        const float2* row = (const float2*)((r < BROWS)
                            ? (src + (size_t)r * DDIM)
                            : (tgt + (size_t)(r - BROWS) * DDIM));
        float sq = 0.0f;
        #pragma unroll
        for (int k = 0; k < 4; k++) {
            int idx = lane + 32 * k;            // float2 index 0..127
            float2 x = row[idx];
            sq = fmaf(x.x, x.x, sq);
            sq = fmaf(x.y, x.y, sq);
            csum[2 * k]     += x.x;
            csum[2 * k + 1] += x.y;
            ((half2*)(g_h + (size_t)r * DDIM))[idx] = __floats2half2_rn(x.x, x.y);
        }
        #pragma unroll
        for (int s = 16; s > 0; s >>= 1) sq += __shfl_xor_sync(0xFFFFFFFFu, sq, s);
        if (lane == 0) { g_sq[r] = sq; s1 += (double)sq; }
    }

    #pragma unroll
    for (int k = 0; k < 4; k++) {
        csum_s[w][64 * k + 2 * lane]     = csum[2 * k];
        csum_s[w][64 * k + 2 * lane + 1] = csum[2 * k + 1];
    }
    if (lane == 0) s1_s[w] = s1;
    __syncthreads();

    float t = 0.0f;
    #pragma unroll
    for (int w2 = 0; w2 < 8; w2++) t += csum_s[w2][tid];
    g_colpart[b][tid] = t;
    if (tid == 0) {
        double bs1 = 0.0;
        #pragma unroll
        for (int w2 = 0; w2 < 8; w2++) bs1 += s1_s[w2];
        g_s1part[b] = bs1;
    }

    __threadfence();
    __syncthreads();
    if (tid == 0) {
        unsigned int old = atomicInc(&g_prep_count, PREPB - 1);
        is_last = (old == PREPB - 1);
    }
    __syncthreads();
    if (!is_last) return;
    __threadfence();

    float cs = 0.0f;
    for (int b2 = 0; b2 < PREPB; b2++) cs += g_colpart[b2][tid];
    double ssq = (double)cs * (double)cs;
    double s1v = g_s1part[tid];

    red_d[tid] = ssq;
    __syncthreads();
    #pragma unroll
    for (int s = 128; s > 0; s >>= 1) {
        if (tid < s) red_d[tid] += red_d[tid + s];
        __syncthreads();
    }
    double ss = red_d[0];
    __syncthreads();
    red_d[tid] = s1v;
    __syncthreads();
    #pragma unroll
    for (int s = 128; s > 0; s >>= 1) {
        if (tid < s) red_d[tid] += red_d[tid + s];
        __syncthreads();
    }
    if (tid == 0) {
        double S1 = red_d[0];
        const double n = (double)NROWS;
        double sum_l2 = 2.0 * n * S1 - 2.0 * ss;
        double bw = sum_l2 / (n * n - n) / 4.0;   // / KERNEL_MUL^(KERNEL_NUM/2)
        g_scale = (float)(1.0 / (bw * 16.0));     // largest sigma = bw*2^4
        g_result = 0.0;
    }
}

// ---------------------------------------------------------------------------
// Issue 8 cp.async (16B) per thread: one KC=64 chunk of A and B fp16 tiles.
__device__ __forceinline__ void prefetch_chunk(
    uint32_t sbase, const __half* A, const __half* B, int k0, int tid) {
    #pragma unroll
    for (int l = 0; l < 4; l++) {
        int f   = tid + l * 256;      // 0..1023
        int r   = f >> 3;             // row 0..127
        int c16 = f & 7;              // 16B group within 128B row
        uint32_t so = (uint32_t)r * ROWB + (uint32_t)c16 * 16;
        size_t  go = (size_t)r * DDIM + k0 + c16 * 8;
        CP_ASYNC16(sbase + so,        (const void*)(A + go));
        CP_ASYNC16(sbase + MATB + so, (const void*)(B + go));
    }
}

__device__ __forceinline__ void decode_tile(int t, int& bi, int& bj) {
    bi = (int)((2.0f * NT + 1.0f
          - sqrtf((float)((2 * NT + 1) * (2 * NT + 1) - 8 * t))) * 0.5f);
    while (bi * NT - bi * (bi - 1) / 2 > t) bi--;
    while ((bi + 1) * NT - (bi + 1) * bi / 2 <= t) bi++;
    bj = bi + t - (bi * NT - bi * (bi - 1) / 2);
}

// ---------------------------------------------------------------------------
// Deterministic grid-stride persistent HMMA pair kernel: CTA b does tiles
// b, b+grid, ... (no atomics on the critical path). f32-acc fp16 mma.sync,
// 3-stage cp.async ring kept warm across tiles, pipelined k-loop, proven
// fp32 epilogue (r13), fused finalize.
__global__ void __launch_bounds__(256, 2)
pair15_kernel(float* __restrict__ out, int grid) {
    extern __shared__ __align__(16) char dyn[];
    __shared__ float sqa[2][BLK];
    __shared__ float sqb[2][BLK];

    int tid  = threadIdx.x;
    int lane = tid & 31;
    int wid  = tid >> 5;
    int wy   = wid >> 2;      // 0..1
    int wx   = wid & 3;       // 0..3

    uint32_t dynb = smem_u32(dyn);

    // Per-lane ldmatrix offsets (bytes) within a matrix buffer
    uint32_t a_off = (uint32_t)(wy * 64 + (lane & 15)) * ROWB + ((lane >> 4) << 4);
    uint32_t b_off = (uint32_t)(wx * 32 + (lane & 7) + ((lane >> 4) << 3)) * ROWB
                   + (((lane >> 3) & 1) << 4);

    // First tile
    int cur = (int)blockIdx.x;
    int biC, bjC;
    decode_tile(cur, biC, bjC);
    const __half* Ac = g_h + (size_t)biC * BLK * DDIM;
    const __half* Bc = g_h + (size_t)bjC * BLK * DDIM;

    prefetch_chunk(dynb + 0 * STAGEB, Ac, Bc, 0, tid);
    CP_COMMIT();
    prefetch_chunk(dynb + 1 * STAGEB, Ac, Bc, KC, tid);
    CP_COMMIT();

    int buf = 0;
    if (tid < BLK) {
        sqa[0][tid] = g_sq[biC * BLK + tid];
        sqb[0][tid] = g_sq[bjC * BLK + tid];
    }

    const float LG2E = 1.4426950408889634f;
    float clg = g_scale * LG2E;
    float f2  = 2.0f * clg;
    int r0 = wy * 64 + (lane >> 2);
    int c0 = wx * 32 + 2 * (lane & 3);

    int stage = 0;
    for (;;) {
        int nxt = cur + grid;
        bool has_nxt = (nxt < NTRI);
        int biN = 0, bjN = 0;
        const __half *An = Ac, *Bn = Bc;
        if (has_nxt) {
            decode_tile(nxt, biN, bjN);
            An = g_h + (size_t)biN * BLK * DDIM;
            Bn = g_h + (size_t)bjN * BLK * DDIM;
        }

        float acc[4][4][4];
        #pragma unroll
        for (int mt = 0; mt < 4; mt++)
            #pragma unroll
            for (int nt = 0; nt < 4; nt++)
                #pragma unroll
                for (int e = 0; e < 4; e++) acc[mt][nt][e] = 0.0f;

        #pragma unroll
        for (int c = 0; c < NCH; c++) {
            CP_WAIT1();              // chunk c of cur complete
            __syncthreads();         // visible to all; ring slot free;
                                     // also: all warps past previous epilogue
            if (c == 0) {
                int ps = stage + 2; if (ps >= NSTAGE) ps -= NSTAGE;
                prefetch_chunk(dynb + ps * STAGEB, Ac, Bc, 2 * KC, tid);
                // safe now: previous epilogue (which read buf^1) is done
                if (has_nxt && tid < BLK) {
                    sqa[buf ^ 1][tid] = g_sq[biN * BLK + tid];
                    sqb[buf ^ 1][tid] = g_sq[bjN * BLK + tid];
                }
            } else if (c == 1) {
                int ps = stage + 2; if (ps >= NSTAGE) ps -= NSTAGE;
                prefetch_chunk(dynb + ps * STAGEB, Ac, Bc, 3 * KC, tid);
            } else if (has_nxt) {
                int ps = stage + 2; if (ps >= NSTAGE) ps -= NSTAGE;
                prefetch_chunk(dynb + ps * STAGEB, An, Bn, (c - 2) * KC, tid);
            }
            CP_COMMIT();             // one group per chunk (possibly empty)

            uint32_t uA = dynb + stage * STAGEB + a_off;
            uint32_t uB = dynb + stage * STAGEB + MATB + b_off;
            if (++stage == NSTAGE) stage = 0;

            // Software-pipelined k-loop: A double-buffered (prefetched before
            // MMAs), B reloaded after MMAs (WAR-safe, hidden under drain).
            uint32_t aF[2][4][4];
            uint32_t bC[2][4];
            #pragma unroll
            for (int bp = 0; bp < 2; bp++)
                ldsm4(bC[bp], uB + (uint32_t)bp * 16 * ROWB);
            #pragma unroll
            for (int mt = 0; mt < 4; mt++)
                ldsm4(aF[0][mt], uA + (uint32_t)mt * 16 * ROWB);

            #pragma unroll
            for (int ks = 0; ks < 4; ks++) {
                const int cb = ks & 1;
                const int nb = cb ^ 1;
                if (ks < 3) {
                    uint32_t kb = (uint32_t)(ks + 1) * 32;
                    #pragma unroll
                    for (int mt = 0; mt < 4; mt++)
                        ldsm4(aF[nb][mt], uA + (uint32_t)mt * 16 * ROWB + kb);
                }
                #pragma unroll
                for (int mt = 0; mt < 4; mt++)
                    #pragma unroll
                    for (int nt = 0; nt < 4; nt++)
                        mma16816(acc[mt][nt], aF[cb][mt],
                                 bC[nt >> 1][(nt & 1) * 2],
                                 bC[nt >> 1][(nt & 1) * 2 + 1]);
                if (ks < 3) {
                    uint32_t kb = (uint32_t)(ks + 1) * 32;
                    #pragma unroll
                    for (int bp = 0; bp < 2; bp++)
                        ldsm4(bC[bp], uB + (uint32_t)bp * 16 * ROWB + kb);
                }
            }
        }

        // Epilogue (proven fp32 path): arg = f2*d - hi - hj (log2 domain),
        // one ex2.approx.ftz.f32 per pair + 4 squarings.
        float hi[8], hj[8];
        #pragma unroll
        for (int mt = 0; mt < 4; mt++) {
            hi[mt * 2]     = clg * sqa[buf][r0 + mt * 16];
            hi[mt * 2 + 1] = clg * sqa[buf][r0 + mt * 16 + 8];
        }
        #pragma unroll
        for (int nt = 0; nt < 4; nt++) {
            hj[nt * 2]     = clg * sqb[buf][c0 + nt * 8];
            hj[nt * 2 + 1] = clg * sqb[buf][c0 + nt * 8 + 1];
        }

        float psum[4] = {0.0f, 0.0f, 0.0f, 0.0f};
        #pragma unroll
        for (int mt = 0; mt < 4; mt++) {
            #pragma unroll
            for (int nt = 0; nt < 4; nt++) {
                #pragma unroll
                for (int e = 0; e < 4; e++) {
                    float d   = acc[mt][nt][e];
                    float arg = fmaf(f2, d,
                                     -(hi[mt * 2 + (e >> 1)] + hj[nt * 2 + (e & 1)]));
                    float e1  = ex2f(arg);
                    float e2  = e1 * e1;
                    float e4  = e2 * e2;
                    float e8  = e4 * e4;
                    float e16 = e8 * e8;
                    psum[mt] += ((e1 + e2) + (e4 + e8)) + e16;
                }
            }
        }
        double local = (double)((psum[0] + psum[1]) + (psum[2] + psum[3]));

        double w = ((biC < NT / 2) == (bjC < NT / 2)) ? 1.0 : -1.0;
        if (bjC > biC) w *= 2.0;
        local *= w;

        #pragma unroll
        for (int s = 16; s > 0; s >>= 1)
            local += __shfl_xor_sync(0xFFFFFFFFu, local, s);
        if (lane == 0) atomicAdd(&g_result, local);

        if (!has_nxt) break;
        cur = nxt; biC = biN; bjC = bjN; Ac = An; Bc = Bn; buf ^= 1;
    }

    // Fused finalize: last CTA to finish writes the output
    if (lane == 0) __threadfence();
    __syncthreads();
    if (tid == 0) {
        unsigned int old = atomicInc(&g_pair_count, (unsigned)grid - 1);
        if (old == (unsigned)grid - 1) {
            __threadfence();
            double r = *((volatile double*)&g_result);
            out[0] = (float)(r * (1.0 / ((double)BROWS * (double)BROWS)));
        }
    }
}

// ---------------------------------------------------------------------------
extern "C" void kernel_launch(void* const* d_in, const int* in_sizes, int n_in,
                              void* d_out, int out_size) {
    const float* src = (const float*)d_in[0];
    const float* tgt = (const float*)d_in[1];
    float* out = (float*)d_out;
    (void)in_sizes; (void)n_in; (void)out_size;

    cudaFuncSetAttribute(pair15_kernel,
                         cudaFuncAttributeMaxDynamicSharedMemorySize, DYN_SMEM);

    int dev = 0, nsm = 148;
    cudaGetDevice(&dev);
    cudaDeviceGetAttribute(&nsm, cudaDevAttrMultiProcessorCount, dev);
    int grid = 2 * nsm;

    prep_kernel<<<PREPB, 256>>>(src, tgt);
    pair15_kernel<<<grid, 256, DYN_SMEM>>>(out, grid);
}